// round 1
// baseline (speedup 1.0000x reference)
#include <cuda_runtime.h>
#include <cstdint>

#define HH 512
#define WW 512
#define WORDS 16                 // uint32 words per image row
#define IMG_WORDS (HH * WORDS)   // 8192 words = 32 KB bit-plane per image

__constant__ int c_R[12] = {0, 1, 1, 1, 0, 2, 2, 2, 0, 3, 3, 3};
__constant__ int c_C[12] = {1, 1, 0, -1, 2, 2, 0, -2, 3, 3, 0, -3};

__global__ __launch_bounds__(1024, 1)
void glcm_kernel(const float* __restrict__ in, float* __restrict__ out)
{
    __shared__ unsigned int sm[IMG_WORDS + 16];  // +pad for w=15 neighbor read
    __shared__ int s_n11[12];
    __shared__ int s_diff[12];

    const int tid  = threadIdx.x;
    const int lane = tid & 31;
    const int warp = tid >> 5;
    const int b    = blockIdx.x;

    if (tid < 12) { s_n11[tid] = 0; s_diff[tid] = 0; }
    if (tid == 0) sm[IMG_WORDS] = 0u;

    // ---------------- Phase 1: pack sign bits into SMEM bit-plane ------------
    // Each warp iteration handles 128 consecutive columns via float4 loads.
    // bit = (x > 0): +1 -> 1, else 0 (sign(0) treated as -1; negligible).
    const float4* img4 = reinterpret_cast<const float4*>(in + (size_t)b * (HH * WW));
    const int NG = (HH * WW) / 128;  // 2048 groups of 128 columns

    #pragma unroll 8
    for (int g = warp; g < NG; g += 32) {
        float4 v = img4[g * 32 + lane];
        unsigned nib = (v.x > 0.0f ? 1u : 0u)
                     | (v.y > 0.0f ? 2u : 0u)
                     | (v.z > 0.0f ? 4u : 0u)
                     | (v.w > 0.0f ? 8u : 0u);
        unsigned pack = nib << ((lane & 7) * 4);
        pack |= __shfl_xor_sync(0xffffffffu, pack, 1);
        pack |= __shfl_xor_sync(0xffffffffu, pack, 2);
        pack |= __shfl_xor_sync(0xffffffffu, pack, 4);
        if ((lane & 7) == 0) sm[g * 4 + (lane >> 3)] = pack;
    }
    __syncthreads();

    // ---------------- Phase 2: popcount sweep over 12 offsets ----------------
    #pragma unroll
    for (int off = 0; off < 12; ++off) {
        const int R = c_R[off];
        const int C = c_C[off];
        const int total = (HH - R) * WORDS;

        unsigned diff = 0, n11 = 0;
        for (int i = tid; i < total; i += 1024) {
            const int w = i & (WORDS - 1);
            const unsigned A = sm[i];
            const int bi = i + R * WORDS;   // same word, R rows down
            unsigned B;
            if (C > 0)       B = __funnelshift_r(sm[bi], sm[bi + 1], C);
            else if (C < 0)  B = __funnelshift_l(sm[bi - 1], sm[bi], -C);
            else             B = sm[bi];

            unsigned m = 0xffffffffu;
            if (C > 0 && w == WORDS - 1) m = 0xffffffffu >> C;    // a cols < W-C
            if (C < 0 && w == 0)         m = 0xffffffffu << (-C); // a cols >= -C

            diff += __popc((A ^ B) & m);
            n11  += __popc((A & B) & m);
        }
        diff = __reduce_add_sync(0xffffffffu, diff);
        n11  = __reduce_add_sync(0xffffffffu, n11);
        if (lane == 0) {
            atomicAdd(&s_diff[off], (int)diff);
            atomicAdd(&s_n11[off], (int)n11);
        }
    }
    __syncthreads();

    // ---------------- Phase 3: normalize & write 48 outputs ------------------
    if (tid < 12) {
        const int R  = c_R[tid];
        const int Cc = c_C[tid];
        const int Ca = Cc < 0 ? -Cc : Cc;
        const int N  = (HH - R) * (WW - Ca);
        const int n11  = s_n11[tid];
        const int diff = s_diff[tid];
        const int n00  = N - n11 - diff;

        const float inv = 1.0f / (float)(2 * N - 4 * n00);
        float* o = out + (size_t)b * 48 + tid * 4;
        o[0] = (float)(4 * n00) * inv;
        const float v1 = (float)(2 * diff - 4 * n00) * inv;
        o[1] = v1;
        o[2] = v1;
        o[3] = (float)(2 * (N - 2 * diff)) * inv;
    }
}

extern "C" void kernel_launch(void* const* d_in, const int* in_sizes, int n_in,
                              void* d_out, int out_size)
{
    (void)n_in; (void)out_size;
    const float* in = (const float*)d_in[0];
    float* out = (float*)d_out;
    const int batch = in_sizes[0] / (HH * WW);   // 128
    glcm_kernel<<<batch, 1024>>>(in, out);
}